// round 10
// baseline (speedup 1.0000x reference)
#include <cuda_runtime.h>
#include <cuda_bf16.h>
#include <math.h>
#include <stdint.h>

#define CC   128
#define TLEN 8192
#define BB   2
#define LL   20
#define TT   64

// smem map (bytes): weights hi (32K) + lo (32K) + act hi (16K) + act lo (16K)
#define SM_W0   0
#define SM_W1   32768
#define SM_ACT  65536
#define ACT_TILE 16384
#define SMEM_TOTAL (SM_ACT + 2 * ACT_TILE)   // 98304

// ---------------- device scratch ----------------
__device__ float g_h0[BB * CC * TLEN];
__device__ float g_h1[BB * CC * TLEN];
// weight images: [l][mat 0..4][hl 0..1][16384 bf16], swizzled [o][c] tile layout
__device__ __nv_bfloat16 g_wimg[LL * 5 * 2 * 16384];

// ---------------- helpers ----------------
__device__ __forceinline__ uint32_t smem_u32(const void* p) {
    uint32_t a;
    asm("{ .reg .u64 t; cvta.to.shared.u64 t, %1; cvt.u32.u64 %0, t; }" : "=r"(a) : "l"(p));
    return a;
}
// cvt.rn.bf16x2.f32 d, a, b : a -> high half, b -> low half
__device__ __forceinline__ uint32_t cvt_bf16x2(float hi, float lo) {
    uint32_t r; asm("cvt.rn.bf16x2.f32 %0, %1, %2;" : "=r"(r) : "f"(hi), "f"(lo)); return r;
}
__device__ __forceinline__ float bflo_f(uint32_t p) { return __uint_as_float(p << 16); }
__device__ __forceinline__ float bfhi_f(uint32_t p) { return __uint_as_float(p & 0xffff0000u); }

#define LDSM4(r, addr) \
    asm volatile("ldmatrix.sync.aligned.m8n8.x4.shared.b16 {%0,%1,%2,%3}, [%4];" \
        : "=r"((r)[0]), "=r"((r)[1]), "=r"((r)[2]), "=r"((r)[3]) : "r"(addr))
#define LDSM4T(r, addr) \
    asm volatile("ldmatrix.sync.aligned.m8n8.x4.trans.shared.b16 {%0,%1,%2,%3}, [%4];" \
        : "=r"((r)[0]), "=r"((r)[1]), "=r"((r)[2]), "=r"((r)[3]) : "r"(addr))
#define STSM4T(addr, r) \
    asm volatile("stmatrix.sync.aligned.m8n8.x4.trans.shared.b16 [%0], {%1,%2,%3,%4};" \
        :: "r"(addr), "r"((r)[0]), "r"((r)[1]), "r"((r)[2]), "r"((r)[3]))
#define MMA_BF16(d, a, b0, b1) \
    asm volatile("mma.sync.aligned.m16n8k16.row.col.f32.bf16.bf16.f32 " \
        "{%0,%1,%2,%3}, {%4,%5,%6,%7}, {%8,%9}, {%0,%1,%2,%3};" \
        : "+f"((d)[0]), "+f"((d)[1]), "+f"((d)[2]), "+f"((d)[3]) \
        : "r"((a)[0]), "r"((a)[1]), "r"((a)[2]), "r"((a)[3]), "r"(b0), "r"(b1))
#define CP_ASYNC16(saddr, gaddr) \
    asm volatile("cp.async.cg.shared.global [%0], [%1], 16;" :: "r"(saddr), "l"(gaddr))
#define CP_COMMIT() asm volatile("cp.async.commit_group;" ::: "memory")
#define CP_WAIT0()  asm volatile("cp.async.wait_group 0;" ::: "memory")

__device__ __forceinline__ float sigmoidf_fast(float v) { return 1.0f / (1.0f + __expf(-v)); }
__device__ __forceinline__ float tanhf_fast(float v) {
    float a = fabsf(v);
    float e = __expf(-2.0f * a);
    float t = (1.0f - e) / (1.0f + e);
    return copysignf(t, v);
}

// ---------------- prep kernels ----------------
// tile layout byte(r, c) = r*256 + (((c>>3) ^ (r&7))<<4) + (c&7)*2
__global__ void prep_weights(const float* __restrict__ w_dil,
                             const float* __restrict__ w_tanh,
                             const float* __restrict__ w_sig,
                             const float* __restrict__ w_skip)
{
    int idx = blockIdx.x * blockDim.x + threadIdx.x;
    if (idx >= LL * 5 * CC * CC) return;
    int k = idx & 127;
    int o = (idx >> 7) & 127;
    int m = (idx >> 14) % 5;
    int l = idx / (5 * CC * CC);
    size_t oc = ((size_t)l * CC + o) * CC + k;
    float v;
    if (m == 0)      v = w_dil[oc * 2 + 0];
    else if (m == 1) v = w_dil[oc * 2 + 1];
    else if (m == 2) v = w_tanh[oc];
    else if (m == 3) v = w_sig[oc];
    else             v = w_skip[oc];
    __nv_bfloat16 hi = __float2bfloat16(v);
    __nv_bfloat16 lo = __float2bfloat16(v - __bfloat162float(hi));
    uint32_t byte = (uint32_t)o * 256 + ((((uint32_t)(k >> 3)) ^ (o & 7)) << 4) + (k & 7) * 2;
    size_t base = ((size_t)(l * 5 + m) * 2) * 16384;
    g_wimg[base + (byte >> 1)]         = hi;
    g_wimg[base + 16384 + (byte >> 1)] = lo;
}

__global__ void input_conv(const float* __restrict__ x,
                           const float* __restrict__ w_in,
                           const float* __restrict__ b_in)
{
    int i4 = blockIdx.x * blockDim.x + threadIdx.x;
    if (i4 >= BB * CC * TLEN / 4) return;
    int t4 = i4 & (TLEN / 4 - 1);
    int c  = (i4 >> 11) & (CC - 1);
    int b  = i4 >> 18;
    float w = w_in[c], bv = b_in[c];
    float4 xv = ((const float4*)x)[(size_t)b * (TLEN / 4) + t4];
    float4 h;
    h.x = fmaf(w, xv.x, bv); h.y = fmaf(w, xv.y, bv);
    h.z = fmaf(w, xv.z, bv); h.w = fmaf(w, xv.w, bv);
    ((float4*)g_h0)[i4] = h;
}

// ---------------- fused 3-term matrix pass ----------------
// acc += Wh@Xh + Wh@Xl + Wl@Xh  (per k-step: 8 LDSM4, 24 MMA)
// 8-warp variant: per warp M=32 (2 mt), N=32 (2 ntp of 16 t)
__device__ __forceinline__ void mma_mat3(float (&acc)[2][4][4],
                                         uint32_t wHi, uint32_t wLo,
                                         uint32_t xH, uint32_t xL,
                                         uint32_t aoff, uint32_t boff,
                                         uint32_t lmask, uint32_t asel, uint32_t bsel)
{
#pragma unroll
    for (int ks = 0; ks < 8; ++ks) {
        uint32_t acu = (((uint32_t)(2 * ks) + asel) << 4) ^ lmask;
        uint32_t ah0[4], ah1[4], al0[4], al1[4];
        LDSM4(ah0, wHi + aoff + acu);
        LDSM4(ah1, wHi + aoff + 4096 + acu);
        LDSM4(al0, wLo + aoff + acu);
        LDSM4(al1, wLo + aoff + 4096 + acu);
        uint32_t bcu = (((uint32_t)(2 * ks) + bsel) << 4) ^ lmask;
#pragma unroll
        for (int ntp = 0; ntp < 2; ++ntp) {
            uint32_t bh[4], bl[4];
            LDSM4(bh, xH + boff + (uint32_t)ntp * 4096 + bcu);
            LDSM4(bl, xL + boff + (uint32_t)ntp * 4096 + bcu);
            MMA_BF16(acc[0][2 * ntp],     ah0, bh[0], bh[1]);
            MMA_BF16(acc[0][2 * ntp + 1], ah0, bh[2], bh[3]);
            MMA_BF16(acc[1][2 * ntp],     ah1, bh[0], bh[1]);
            MMA_BF16(acc[1][2 * ntp + 1], ah1, bh[2], bh[3]);
            MMA_BF16(acc[0][2 * ntp],     ah0, bl[0], bl[1]);
            MMA_BF16(acc[0][2 * ntp + 1], ah0, bl[2], bl[3]);
            MMA_BF16(acc[1][2 * ntp],     ah1, bl[0], bl[1]);
            MMA_BF16(acc[1][2 * ntp + 1], ah1, bl[2], bl[3]);
            MMA_BF16(acc[0][2 * ntp],     al0, bh[0], bh[1]);
            MMA_BF16(acc[0][2 * ntp + 1], al0, bh[2], bh[3]);
            MMA_BF16(acc[1][2 * ntp],     al1, bh[0], bh[1]);
            MMA_BF16(acc[1][2 * ntp + 1], al1, bh[2], bh[3]);
        }
    }
}

// ---------------- fused layer kernel (256 thr, 2 blocks/SM) ----------------
__global__ void __launch_bounds__(256, 2)
layer_kernel(int layer, int dil, int ping,
             const float* __restrict__ b_dil, const float* __restrict__ b_tanh,
             const float* __restrict__ b_sig, const float* __restrict__ b_skip,
             float* __restrict__ out_base)
{
    extern __shared__ char smem[];
    const uint32_t sb = smem_u32(smem);
    const int tid = threadIdx.x;
    const int wid = tid >> 5, lane = tid & 31;
    const int wm = wid & 3, wn = wid >> 2;     // wm 0..3 (o, 32 each), wn 0..1 (t, 32 each)

    const float* hin  = ping ? g_h1 : g_h0;
    float*       hout = ping ? g_h0 : g_h1;
    const int blk = blockIdx.x;
    const int b   = blk >> 7;                  // 128 tiles per sample
    const int t0  = (blk & 127) * TT;
    const float* hbase = hin + (size_t)b * CC * TLEN;
    float* hob     = hout + (size_t)b * CC * TLEN;
    float* outputs = out_base + ((size_t)layer * BB + b) * CC * TLEN;
    float* skips   = out_base + (size_t)LL * BB * CC * TLEN + ((size_t)layer * BB + b) * CC * TLEN;

    // prefetch matrix m (hi -> W0, lo -> W1): 32KB each, 256 thr * 16B = 4KB/iter
    auto prefetch_mat = [&](int m) {
        const char* gh = (const char*)(g_wimg + ((size_t)(layer * 5 + m) * 2 + 0) * 16384);
        const char* gl = (const char*)(g_wimg + ((size_t)(layer * 5 + m) * 2 + 1) * 16384);
#pragma unroll
        for (int j = 0; j < 8; ++j)
            CP_ASYNC16(sb + SM_W0 + tid * 16 + j * 4096, gh + tid * 16 + j * 4096);
#pragma unroll
        for (int j = 0; j < 8; ++j)
            CP_ASYNC16(sb + SM_W1 + tid * 16 + j * 4096, gl + tid * 16 + j * 4096);
        CP_COMMIT();
    };

    // ---- per-thread staging constants
    const int st_t   = tid & 63;
    const int quar   = tid >> 6;               // 0..3 -> 32 channels
    const uint32_t rowbase = (uint32_t)st_t * 256;
    const uint32_t rmask   = (uint32_t)(st_t & 7);

    // stage one [64t][128c] tile pair from column base ptr (ptr = base + t index), opt zero-guard
    auto stage = [&](const float* src, bool valid) {
#pragma unroll
        for (int jb = 0; jb < 4; ++jb) {
            int cc0 = quar * 32 + jb * 8;
            uint32_t hreg[4], lreg[4];
#pragma unroll
            for (int e = 0; e < 4; ++e) {
                float v0 = valid ? __ldg(src + (size_t)(cc0 + 2 * e) * TLEN) : 0.0f;
                float v1 = valid ? __ldg(src + (size_t)(cc0 + 2 * e + 1) * TLEN) : 0.0f;
                uint32_t h2 = cvt_bf16x2(v1, v0);
                hreg[e] = h2;
                lreg[e] = cvt_bf16x2(v1 - bfhi_f(h2), v0 - bflo_f(h2));
            }
            uint32_t unit = (((uint32_t)(cc0 >> 3)) ^ rmask) << 4;
            char* base = smem + SM_ACT + rowbase + unit;
            *(uint4*)(base)            = make_uint4(hreg[0], hreg[1], hreg[2], hreg[3]);
            *(uint4*)(base + ACT_TILE) = make_uint4(lreg[0], lreg[1], lreg[2], lreg[3]);
        }
    };

    // per-lane MMA invariants
    const uint32_t lmask = (uint32_t)(lane & 7) << 4;
    const uint32_t asel = (uint32_t)((lane >> 4) & 1);
    const uint32_t bsel = (uint32_t)((lane >> 3) & 1);
    const uint32_t aoff = (uint32_t)(wm * 32 + (lane & 7) + ((lane >> 3) & 1) * 8) * 256;
    const uint32_t boff = (uint32_t)(wn * 32 + (lane & 7) + ((lane >> 4) & 1) * 8) * 256;
    uint32_t sunit[2];
#pragma unroll
    for (int mt = 0; mt < 2; ++mt)
        sunit[mt] = (((uint32_t)(wm * 4 + mt * 2 + ((lane >> 3) & 1))) << 4) ^ lmask;

    const uint32_t xH = sb + SM_ACT;
    const uint32_t xL = xH + ACT_TILE;
    const uint32_t wHi = sb + SM_W0, wLo = sb + SM_W1;

    float acc[2][4][4];
    float flt[2][4][4];

    auto init_acc = [&](float (&A)[2][4][4], const float* bias) {
#pragma unroll
        for (int mt = 0; mt < 2; ++mt) {
            float v0 = __ldg(bias + wm * 32 + mt * 16 + (lane >> 2));
            float v1 = __ldg(bias + wm * 32 + mt * 16 + 8 + (lane >> 2));
#pragma unroll
            for (int nt = 0; nt < 4; ++nt) {
                A[mt][nt][0] = v0; A[mt][nt][1] = v0;
                A[mt][nt][2] = v1; A[mt][nt][3] = v1;
            }
        }
    };

    // ======== phase 1: GEMM1 term W1 @ hcur ========
    prefetch_mat(1);                         // w_dil tap 1 (current)
    // stage hcur (+ fused outputs copy)
    {
        const float* hsrc = hbase + t0 + st_t;
        float* outp = outputs + t0 + st_t;
#pragma unroll
        for (int jb = 0; jb < 4; ++jb) {
            int cc0 = quar * 32 + jb * 8;
            uint32_t hreg[4], lreg[4];
#pragma unroll
            for (int e = 0; e < 4; ++e) {
                float v0 = __ldg(hsrc + (size_t)(cc0 + 2 * e) * TLEN);
                float v1 = __ldg(hsrc + (size_t)(cc0 + 2 * e + 1) * TLEN);
                outp[(size_t)(cc0 + 2 * e) * TLEN]     = v0;
                outp[(size_t)(cc0 + 2 * e + 1) * TLEN] = v1;
                uint32_t h2 = cvt_bf16x2(v1, v0);
                hreg[e] = h2;
                lreg[e] = cvt_bf16x2(v1 - bfhi_f(h2), v0 - bflo_f(h2));
            }
            uint32_t unit = (((uint32_t)(cc0 >> 3)) ^ rmask) << 4;
            char* base = smem + SM_ACT + rowbase + unit;
            *(uint4*)(base)            = make_uint4(hreg[0], hreg[1], hreg[2], hreg[3]);
            *(uint4*)(base + ACT_TILE) = make_uint4(lreg[0], lreg[1], lreg[2], lreg[3]);
        }
    }
    init_acc(acc, b_dil + layer * CC);
    CP_WAIT0();
    __syncthreads();
    mma_mat3(acc, wHi, wLo, xH, xL, aoff, boff, lmask, asel, bsel);
    __syncthreads();                         // done reading tiles + W

    // ======== phase 2: GEMM1 term W0 @ hdel ========
    prefetch_mat(0);                         // w_dil tap 0 (delayed)
    stage(hbase + t0 + st_t - dil, (t0 + st_t - dil) >= 0);
    CP_WAIT0();
    __syncthreads();
    mma_mat3(acc, wHi, wLo, xH, xL, aoff, boff, lmask, asel, bsel);
    __syncthreads();                         // done reading hdel tiles + W

    // ======== epi1: xdil -> tiles (hi/lo) ========
    prefetch_mat(2);                         // w_tanh
#pragma unroll
    for (int mt = 0; mt < 2; ++mt)
#pragma unroll
        for (int ntp = 0; ntp < 2; ++ntp) {
            uint32_t rh[4], rl[4];
#pragma unroll
            for (int q = 0; q < 4; ++q) {
                float d0 = acc[mt][2 * ntp + (q >> 1)][(q & 1) * 2 + 0];
                float d1 = acc[mt][2 * ntp + (q >> 1)][(q & 1) * 2 + 1];
                uint32_t h = cvt_bf16x2(d1, d0);
                rh[q] = h;
                rl[q] = cvt_bf16x2(d1 - bfhi_f(h), d0 - bflo_f(h));
            }
            uint32_t ad = boff + (uint32_t)ntp * 4096 + sunit[mt];
            STSM4T(xH + ad, rh);
            STSM4T(xL + ad, rl);
        }
    CP_WAIT0();
    __syncthreads();                         // xdil visible + W2 ready

    // ======== phase 3: filt = tanh(Wt @ xdil) (kept in regs) ========
    init_acc(acc, b_tanh + layer * CC);
    mma_mat3(acc, wHi, wLo, xH, xL, aoff, boff, lmask, asel, bsel);
#pragma unroll
    for (int mt = 0; mt < 2; ++mt)
#pragma unroll
        for (int nt = 0; nt < 4; ++nt)
#pragma unroll
            for (int q = 0; q < 4; ++q)
                flt[mt][nt][q] = tanhf_fast(acc[mt][nt][q]);
    __syncthreads();                         // done reading W2 (tiles unchanged)

    // ======== phase 4: gate GEMM + xh + h_next ========
    prefetch_mat(3);                         // w_sig
    init_acc(acc, b_sig + layer * CC);
    CP_WAIT0();
    __syncthreads();
    mma_mat3(acc, wHi, wLo, xH, xL, aoff, boff, lmask, asel, bsel);
    // epi: xh = filt * sigmoid(gate); h_next = xh + xdil -> global; xh -> flt regs
#pragma unroll
    for (int mt = 0; mt < 2; ++mt)
#pragma unroll
        for (int ntp = 0; ntp < 2; ++ntp) {
            uint32_t ad = boff + (uint32_t)ntp * 4096 + sunit[mt];
            uint32_t xdh[4], xdl[4];
            LDSM4T(xdh, xH + ad);
            LDSM4T(xdl, xL + ad);
#pragma unroll
            for (int q = 0; q < 4; ++q) {
                int nt = 2 * ntp + (q >> 1), hh = q & 1;
                float xd0 = bflo_f(xdh[q]) + bflo_f(xdl[q]);
                float xd1 = bfhi_f(xdh[q]) + bfhi_f(xdl[q]);
                float g0 = sigmoidf_fast(acc[mt][nt][hh * 2 + 0]);
                float g1 = sigmoidf_fast(acc[mt][nt][hh * 2 + 1]);
                float xh0 = flt[mt][nt][hh * 2 + 0] * g0;
                float xh1 = flt[mt][nt][hh * 2 + 1] * g1;
                int o  = wm * 32 + mt * 16 + hh * 8 + (lane >> 2);
                int tg = t0 + wn * 32 + nt * 8 + (lane & 3) * 2;
                *(float2*)(hob + (size_t)o * TLEN + tg) = make_float2(xh0 + xd0, xh1 + xd1);
                flt[mt][nt][hh * 2 + 0] = xh0;
                flt[mt][nt][hh * 2 + 1] = xh1;
            }
        }
    __syncthreads();                         // all done reading tiles (MMA + LDSM4T) + W3

    // ======== phase 5: xh -> tiles; skip GEMM ========
    prefetch_mat(4);                         // w_skip
#pragma unroll
    for (int mt = 0; mt < 2; ++mt)
#pragma unroll
        for (int ntp = 0; ntp < 2; ++ntp) {
            uint32_t rh[4], rl[4];
#pragma unroll
            for (int q = 0; q < 4; ++q) {
                float x0 = flt[mt][2 * ntp + (q >> 1)][(q & 1) * 2 + 0];
                float x1 = flt[mt][2 * ntp + (q >> 1)][(q & 1) * 2 + 1];
                uint32_t h = cvt_bf16x2(x1, x0);
                rh[q] = h;
                rl[q] = cvt_bf16x2(x1 - bfhi_f(h), x0 - bflo_f(h));
            }
            uint32_t ad = boff + (uint32_t)ntp * 4096 + sunit[mt];
            STSM4T(xH + ad, rh);
            STSM4T(xL + ad, rl);
        }
    init_acc(acc, b_skip + layer * CC);
    CP_WAIT0();
    __syncthreads();
    mma_mat3(acc, wHi, wLo, xH, xL, aoff, boff, lmask, asel, bsel);
#pragma unroll
    for (int mt = 0; mt < 2; ++mt)
#pragma unroll
        for (int nt = 0; nt < 4; ++nt)
#pragma unroll
            for (int hh = 0; hh < 2; ++hh) {
                int o  = wm * 32 + mt * 16 + hh * 8 + (lane >> 2);
                int tg = t0 + wn * 32 + nt * 8 + (lane & 3) * 2;
                *(float2*)(skips + (size_t)o * TLEN + tg) =
                    make_float2(acc[mt][nt][hh * 2 + 0], acc[mt][nt][hh * 2 + 1]);
            }
}

// ---------------- host ----------------
extern "C" void kernel_launch(void* const* d_in, const int* in_sizes, int n_in,
                              void* d_out, int out_size)
{
    const float* x      = (const float*)d_in[0];
    const float* w_in   = (const float*)d_in[1];
    const float* b_in   = (const float*)d_in[2];
    const float* w_dil  = (const float*)d_in[3];
    const float* b_dil  = (const float*)d_in[4];
    const float* w_tanh = (const float*)d_in[5];
    const float* b_tanh = (const float*)d_in[6];
    const float* w_sig  = (const float*)d_in[7];
    const float* b_sig  = (const float*)d_in[8];
    const float* w_skip = (const float*)d_in[9];
    const float* b_skip = (const float*)d_in[10];
    float* out = (float*)d_out;

    cudaFuncSetAttribute(layer_kernel,
                         cudaFuncAttributeMaxDynamicSharedMemorySize, SMEM_TOTAL);

    prep_weights<<<(LL * 5 * CC * CC + 255) / 256, 256>>>(w_dil, w_tanh, w_sig, w_skip);
    input_conv<<<(BB * CC * TLEN / 4 + 255) / 256, 256>>>(x, w_in, b_in);

    const int dils[LL] = {1, 2, 4, 8, 16, 32, 64, 128, 256, 512,
                          1, 2, 4, 8, 16, 32, 64, 128, 256, 512};
    for (int i = 0; i < LL; ++i) {
        layer_kernel<<<(BB * TLEN) / TT, 256, SMEM_TOTAL>>>(
            i, dils[i], i & 1, b_dil, b_tanh, b_sig, b_skip, out);
    }
}

// round 11
// speedup vs baseline: 1.5044x; 1.5044x over previous
#include <cuda_runtime.h>
#include <cuda_bf16.h>
#include <math.h>
#include <stdint.h>

#define CC   128
#define TLEN 8192
#define BB   2
#define LL   20
#define TT   128

// smem map (bytes): weight pairs P0/P1 (4 x 32KB) + act tiles X_h, X_l, T3
#define SM_P0H  0
#define SM_P0L  32768
#define SM_P1H  65536
#define SM_P1L  98304
#define SM_XH   131072
#define SM_XL   163840
#define SM_T3   196608
#define SMEM_TOTAL 229376   // 224 KB

// ---------------- device scratch ----------------
__device__ float g_h0[BB * CC * TLEN];
__device__ float g_h1[BB * CC * TLEN];
// weight images: [l][mat 0..4][hl 0..1][16384 bf16], swizzled [o][c] tile layout
__device__ __nv_bfloat16 g_wimg[LL * 5 * 2 * 16384];

// ---------------- helpers ----------------
__device__ __forceinline__ uint32_t smem_u32(const void* p) {
    uint32_t a;
    asm("{ .reg .u64 t; cvta.to.shared.u64 t, %1; cvt.u32.u64 %0, t; }" : "=r"(a) : "l"(p));
    return a;
}
// cvt.rn.bf16x2.f32 d, a, b : a -> high half, b -> low half
__device__ __forceinline__ uint32_t cvt_bf16x2(float hi, float lo) {
    uint32_t r; asm("cvt.rn.bf16x2.f32 %0, %1, %2;" : "=r"(r) : "f"(hi), "f"(lo)); return r;
}
__device__ __forceinline__ float bflo_f(uint32_t p) { return __uint_as_float(p << 16); }
__device__ __forceinline__ float bfhi_f(uint32_t p) { return __uint_as_float(p & 0xffff0000u); }

#define LDSM4(r, addr) \
    asm volatile("ldmatrix.sync.aligned.m8n8.x4.shared.b16 {%0,%1,%2,%3}, [%4];" \
        : "=r"((r)[0]), "=r"((r)[1]), "=r"((r)[2]), "=r"((r)[3]) : "r"(addr))
#define LDSM4T(r, addr) \
    asm volatile("ldmatrix.sync.aligned.m8n8.x4.trans.shared.b16 {%0,%1,%2,%3}, [%4];" \
        : "=r"((r)[0]), "=r"((r)[1]), "=r"((r)[2]), "=r"((r)[3]) : "r"(addr))
#define STSM4T(addr, r) \
    asm volatile("stmatrix.sync.aligned.m8n8.x4.trans.shared.b16 [%0], {%1,%2,%3,%4};" \
        :: "r"(addr), "r"((r)[0]), "r"((r)[1]), "r"((r)[2]), "r"((r)[3]))
#define MMA_BF16(d, a, b0, b1) \
    asm volatile("mma.sync.aligned.m16n8k16.row.col.f32.bf16.bf16.f32 " \
        "{%0,%1,%2,%3}, {%4,%5,%6,%7}, {%8,%9}, {%0,%1,%2,%3};" \
        : "+f"((d)[0]), "+f"((d)[1]), "+f"((d)[2]), "+f"((d)[3]) \
        : "r"((a)[0]), "r"((a)[1]), "r"((a)[2]), "r"((a)[3]), "r"(b0), "r"(b1))
#define CP_ASYNC16(saddr, gaddr) \
    asm volatile("cp.async.cg.shared.global [%0], [%1], 16;" :: "r"(saddr), "l"(gaddr))
#define CP_COMMIT() asm volatile("cp.async.commit_group;" ::: "memory")
#define CP_WAIT(n)  asm volatile("cp.async.wait_group %0;" :: "n"(n) : "memory")

__device__ __forceinline__ float sigmoidf_fast(float v) { return 1.0f / (1.0f + __expf(-v)); }
__device__ __forceinline__ float tanhf_fast(float v) {
    float a = fabsf(v);
    float e = __expf(-2.0f * a);
    float t = (1.0f - e) / (1.0f + e);
    return copysignf(t, v);
}

// ---------------- prep kernels ----------------
// tile layout byte(r, c) = r*256 + (((c>>3) ^ (r&7))<<4) + (c&7)*2
__global__ void prep_weights(const float* __restrict__ w_dil,
                             const float* __restrict__ w_tanh,
                             const float* __restrict__ w_sig,
                             const float* __restrict__ w_skip)
{
    int idx = blockIdx.x * blockDim.x + threadIdx.x;
    if (idx >= LL * 5 * CC * CC) return;
    int k = idx & 127;
    int o = (idx >> 7) & 127;
    int m = (idx >> 14) % 5;
    int l = idx / (5 * CC * CC);
    size_t oc = ((size_t)l * CC + o) * CC + k;
    float v;
    if (m == 0)      v = w_dil[oc * 2 + 0];
    else if (m == 1) v = w_dil[oc * 2 + 1];
    else if (m == 2) v = w_tanh[oc];
    else if (m == 3) v = w_sig[oc];
    else             v = w_skip[oc];
    __nv_bfloat16 hi = __float2bfloat16(v);
    __nv_bfloat16 lo = __float2bfloat16(v - __bfloat162float(hi));
    uint32_t byte = (uint32_t)o * 256 + ((((uint32_t)(k >> 3)) ^ (o & 7)) << 4) + (k & 7) * 2;
    size_t base = ((size_t)(l * 5 + m) * 2) * 16384;
    g_wimg[base + (byte >> 1)]         = hi;
    g_wimg[base + 16384 + (byte >> 1)] = lo;
}

__global__ void input_conv(const float* __restrict__ x,
                           const float* __restrict__ w_in,
                           const float* __restrict__ b_in)
{
    int i4 = blockIdx.x * blockDim.x + threadIdx.x;
    if (i4 >= BB * CC * TLEN / 4) return;
    int t4 = i4 & (TLEN / 4 - 1);
    int c  = (i4 >> 11) & (CC - 1);
    int b  = i4 >> 18;
    float w = w_in[c], bv = b_in[c];
    float4 xv = ((const float4*)x)[(size_t)b * (TLEN / 4) + t4];
    float4 h;
    h.x = fmaf(w, xv.x, bv); h.y = fmaf(w, xv.y, bv);
    h.z = fmaf(w, xv.z, bv); h.w = fmaf(w, xv.w, bv);
    ((float4*)g_h0)[i4] = h;
}

// ---------------- fused 3-term matrix pass ----------------
// acc += Wh@Xh + Wh@Xl + Wl@Xh  (per k-step: 8 LDSM4, 24 MMA)
// 16-warp variant: per warp M=32 (2 mt), N=32 (2 ntp)
__device__ __forceinline__ void mma_mat3(float (&acc)[2][4][4],
                                         uint32_t wHi, uint32_t wLo,
                                         uint32_t xH, uint32_t xL,
                                         uint32_t aoff, uint32_t boff,
                                         uint32_t lmask, uint32_t asel, uint32_t bsel)
{
#pragma unroll
    for (int ks = 0; ks < 8; ++ks) {
        uint32_t acu = (((uint32_t)(2 * ks) + asel) << 4) ^ lmask;
        uint32_t ah0[4], ah1[4], al0[4], al1[4];
        LDSM4(ah0, wHi + aoff + acu);
        LDSM4(ah1, wHi + aoff + 4096 + acu);
        LDSM4(al0, wLo + aoff + acu);
        LDSM4(al1, wLo + aoff + 4096 + acu);
        uint32_t bcu = (((uint32_t)(2 * ks) + bsel) << 4) ^ lmask;
#pragma unroll
        for (int ntp = 0; ntp < 2; ++ntp) {
            uint32_t bh[4], bl[4];
            LDSM4(bh, xH + boff + (uint32_t)ntp * 4096 + bcu);
            LDSM4(bl, xL + boff + (uint32_t)ntp * 4096 + bcu);
            MMA_BF16(acc[0][2 * ntp],     ah0, bh[0], bh[1]);
            MMA_BF16(acc[0][2 * ntp + 1], ah0, bh[2], bh[3]);
            MMA_BF16(acc[1][2 * ntp],     ah1, bh[0], bh[1]);
            MMA_BF16(acc[1][2 * ntp + 1], ah1, bh[2], bh[3]);
            MMA_BF16(acc[0][2 * ntp],     ah0, bl[0], bl[1]);
            MMA_BF16(acc[0][2 * ntp + 1], ah0, bl[2], bl[3]);
            MMA_BF16(acc[1][2 * ntp],     ah1, bl[0], bl[1]);
            MMA_BF16(acc[1][2 * ntp + 1], ah1, bl[2], bl[3]);
            MMA_BF16(acc[0][2 * ntp],     al0, bh[0], bh[1]);
            MMA_BF16(acc[0][2 * ntp + 1], al0, bh[2], bh[3]);
            MMA_BF16(acc[1][2 * ntp],     al1, bh[0], bh[1]);
            MMA_BF16(acc[1][2 * ntp + 1], al1, bh[2], bh[3]);
        }
    }
}

// ---------------- fused layer kernel (512 thr, weights double-buffered) ----------------
__global__ void __launch_bounds__(512, 1)
layer_kernel(int layer, int dil, int ping,
             const float* __restrict__ b_dil, const float* __restrict__ b_tanh,
             const float* __restrict__ b_sig, const float* __restrict__ b_skip,
             float* __restrict__ out_base)
{
    extern __shared__ char smem[];
    const uint32_t sb = smem_u32(smem);
    const int tid = threadIdx.x;
    const int wid = tid >> 5, lane = tid & 31;
    const int wm = wid & 3, wn = wid >> 2;     // wm 0..3 (o, 32 each), wn 0..3 (t, 32 each)

    const float* hin  = ping ? g_h1 : g_h0;
    float*       hout = ping ? g_h0 : g_h1;
    const int blk = blockIdx.x;
    const int b   = blk >> 6;
    const int t0  = (blk & 63) * TT;
    const float* hbase = hin + (size_t)b * CC * TLEN;
    float* hob     = hout + (size_t)b * CC * TLEN;
    float* outputs = out_base + ((size_t)layer * BB + b) * CC * TLEN;
    float* skips   = out_base + (size_t)LL * BB * CC * TLEN + ((size_t)layer * BB + b) * CC * TLEN;

    // prefetch matrix m (hi+lo = 64KB) into pair p; one commit group
    auto prefetch_mat = [&](int m, int p) {
        const char* gh = (const char*)(g_wimg + ((size_t)(layer * 5 + m) * 2 + 0) * 16384);
        const char* gl = (const char*)(g_wimg + ((size_t)(layer * 5 + m) * 2 + 1) * 16384);
        uint32_t dh = sb + (p ? SM_P1H : SM_P0H);
        uint32_t dl = sb + (p ? SM_P1L : SM_P0L);
#pragma unroll
        for (int j = 0; j < 4; ++j)
            CP_ASYNC16(dh + tid * 16 + j * 8192, gh + tid * 16 + j * 8192);
#pragma unroll
        for (int j = 0; j < 4; ++j)
            CP_ASYNC16(dl + tid * 16 + j * 8192, gl + tid * 16 + j * 8192);
        CP_COMMIT();
    };

    // ---- per-thread staging constants (512 thr: 128 t x 32 ch per thread-row)
    const int st_t = tid & 127;
    const int quar = tid >> 7;                  // 0..3 -> 32 channels
    const uint32_t rowbase = (uint32_t)st_t * 256;
    const uint32_t rmask   = (uint32_t)(st_t & 7);

    // stage a [128t][128c] tile pair: src column ptr = base + t; optional zero-guard
    auto stage = [&](const float* src, bool valid, uint32_t dsth, uint32_t dstl) {
#pragma unroll
        for (int jb = 0; jb < 4; ++jb) {
            int cc0 = quar * 32 + jb * 8;
            uint32_t hreg[4], lreg[4];
#pragma unroll
            for (int e = 0; e < 4; ++e) {
                float v0 = valid ? __ldg(src + (size_t)(cc0 + 2 * e) * TLEN) : 0.0f;
                float v1 = valid ? __ldg(src + (size_t)(cc0 + 2 * e + 1) * TLEN) : 0.0f;
                uint32_t h2 = cvt_bf16x2(v1, v0);
                hreg[e] = h2;
                lreg[e] = cvt_bf16x2(v1 - bfhi_f(h2), v0 - bflo_f(h2));
            }
            uint32_t unit = (((uint32_t)(cc0 >> 3)) ^ rmask) << 4;
            *(uint4*)(smem + (dsth - sb) + rowbase + unit) =
                make_uint4(hreg[0], hreg[1], hreg[2], hreg[3]);
            *(uint4*)(smem + (dstl - sb) + rowbase + unit) =
                make_uint4(lreg[0], lreg[1], lreg[2], lreg[3]);
        }
    };

    // per-lane MMA invariants
    const uint32_t lmask = (uint32_t)(lane & 7) << 4;
    const uint32_t asel = (uint32_t)((lane >> 4) & 1);
    const uint32_t bsel = (uint32_t)((lane >> 3) & 1);
    const uint32_t aoff = (uint32_t)(wm * 32 + (lane & 7) + ((lane >> 3) & 1) * 8) * 256;
    const uint32_t boff = (uint32_t)(wn * 32 + (lane & 7) + ((lane >> 4) & 1) * 8) * 256;
    uint32_t sunit[2];
#pragma unroll
    for (int mt = 0; mt < 2; ++mt)
        sunit[mt] = (((uint32_t)(wm * 4 + mt * 2 + ((lane >> 3) & 1))) << 4) ^ lmask;

    const uint32_t P0h = sb + SM_P0H, P0l = sb + SM_P0L;
    const uint32_t P1h = sb + SM_P1H, P1l = sb + SM_P1L;
    const uint32_t Xh = sb + SM_XH, Xl = sb + SM_XL, T3 = sb + SM_T3;

    float acc[2][4][4];
    float flt[2][4][4];

    auto init_acc = [&](const float* bias) {
#pragma unroll
        for (int mt = 0; mt < 2; ++mt) {
            float v0 = __ldg(bias + wm * 32 + mt * 16 + (lane >> 2));
            float v1 = __ldg(bias + wm * 32 + mt * 16 + 8 + (lane >> 2));
#pragma unroll
            for (int nt = 0; nt < 4; ++nt) {
                acc[mt][nt][0] = v0; acc[mt][nt][1] = v0;
                acc[mt][nt][2] = v1; acc[mt][nt][3] = v1;
            }
        }
    };

    // ======== prefetch first two weight mats ========
    prefetch_mat(1, 0);   // commit 1: w_dil tap-1 (current)  -> P0
    prefetch_mat(0, 1);   // commit 2: w_dil tap-0 (delayed)  -> P1

    // ======== stage hcur -> (Xh, Xl), fused outputs copy ========
    {
        const float* hsrc = hbase + t0 + st_t;
        float* outp = outputs + t0 + st_t;
#pragma unroll
        for (int jb = 0; jb < 4; ++jb) {
            int cc0 = quar * 32 + jb * 8;
            uint32_t hreg[4], lreg[4];
#pragma unroll
            for (int e = 0; e < 4; ++e) {
                float v0 = __ldg(hsrc + (size_t)(cc0 + 2 * e) * TLEN);
                float v1 = __ldg(hsrc + (size_t)(cc0 + 2 * e + 1) * TLEN);
                outp[(size_t)(cc0 + 2 * e) * TLEN]     = v0;
                outp[(size_t)(cc0 + 2 * e + 1) * TLEN] = v1;
                uint32_t h2 = cvt_bf16x2(v1, v0);
                hreg[e] = h2;
                lreg[e] = cvt_bf16x2(v1 - bfhi_f(h2), v0 - bflo_f(h2));
            }
            uint32_t unit = (((uint32_t)(cc0 >> 3)) ^ rmask) << 4;
            *(uint4*)(smem + SM_XH + rowbase + unit) = make_uint4(hreg[0], hreg[1], hreg[2], hreg[3]);
            *(uint4*)(smem + SM_XL + rowbase + unit) = make_uint4(lreg[0], lreg[1], lreg[2], lreg[3]);
        }
    }
    init_acc(b_dil + layer * CC);

    // ======== G1a: acc += W1 (x) hcur ========
    CP_WAIT(1);               // mat1 (P0) ready; mat0 (P1) may be in flight
    __syncthreads();
    mma_mat3(acc, P0h, P0l, Xh, Xl, aoff, boff, lmask, asel, bsel);
    __syncthreads();          // P0 + X tiles free

    // ======== G1b: acc += W0 (x) hdel ========
    prefetch_mat(2, 0);       // commit 3: w_tanh -> P0
    stage(hbase + t0 + st_t - dil, (t0 + st_t - dil) >= 0, T3, Xl);   // hdel -> (T3, Xl)
    CP_WAIT(1);               // mat0 (P1) ready; mat2 pending
    __syncthreads();
    mma_mat3(acc, P1h, P1l, T3, Xl, aoff, boff, lmask, asel, bsel);
    __syncthreads();          // P1 + hdel tiles free

    // ======== epi1: xdil -> (Xh, Xl) ========
    prefetch_mat(3, 1);       // commit 4: w_sig -> P1
#pragma unroll
    for (int mt = 0; mt < 2; ++mt)
#pragma unroll
        for (int ntp = 0; ntp < 2; ++ntp) {
            uint32_t rh[4], rl[4];
#pragma unroll
            for (int q = 0; q < 4; ++q) {
                float d0 = acc[mt][2 * ntp + (q >> 1)][(q & 1) * 2 + 0];
                float d1 = acc[mt][2 * ntp + (q >> 1)][(q & 1) * 2 + 1];
                uint32_t h = cvt_bf16x2(d1, d0);
                rh[q] = h;
                rl[q] = cvt_bf16x2(d1 - bfhi_f(h), d0 - bflo_f(h));
            }
            uint32_t ad = boff + (uint32_t)ntp * 4096 + sunit[mt];
            STSM4T(Xh + ad, rh);
            STSM4T(Xl + ad, rl);
        }
    CP_WAIT(1);               // mat2 (P0) ready; mat3 pending
    __syncthreads();          // xdil visible

    // ======== G2: filt = tanh(Wt (x) xdil), kept in regs ========
    init_acc(b_tanh + layer * CC);
    mma_mat3(acc, P0h, P0l, Xh, Xl, aoff, boff, lmask, asel, bsel);
#pragma unroll
    for (int mt = 0; mt < 2; ++mt)
#pragma unroll
        for (int nt = 0; nt < 4; ++nt)
#pragma unroll
            for (int q = 0; q < 4; ++q)
                flt[mt][nt][q] = tanhf_fast(acc[mt][nt][q]);
    __syncthreads();          // P0 free (X tiles unchanged)

    // ======== G3: gate; h_next -> global; xh into flt ========
    prefetch_mat(4, 0);       // commit 5: w_skip -> P0
    init_acc(b_sig + layer * CC);
    CP_WAIT(1);               // mat3 (P1) ready; mat4 pending
    __syncthreads();
    mma_mat3(acc, P1h, P1l, Xh, Xl, aoff, boff, lmask, asel, bsel);
#pragma unroll
    for (int mt = 0; mt < 2; ++mt)
#pragma unroll
        for (int ntp = 0; ntp < 2; ++ntp) {
            uint32_t ad = boff + (uint32_t)ntp * 4096 + sunit[mt];
            uint32_t xdh[4], xdl[4];
            LDSM4T(xdh, Xh + ad);
            LDSM4T(xdl, Xl + ad);
#pragma unroll
            for (int q = 0; q < 4; ++q) {
                int nt = 2 * ntp + (q >> 1), hh = q & 1;
                float xd0 = bflo_f(xdh[q]) + bflo_f(xdl[q]);
                float xd1 = bfhi_f(xdh[q]) + bfhi_f(xdl[q]);
                float g0 = sigmoidf_fast(acc[mt][nt][hh * 2 + 0]);
                float g1 = sigmoidf_fast(acc[mt][nt][hh * 2 + 1]);
                float xh0 = flt[mt][nt][hh * 2 + 0] * g0;
                float xh1 = flt[mt][nt][hh * 2 + 1] * g1;
                int o  = wm * 32 + mt * 16 + hh * 8 + (lane >> 2);
                int tg = t0 + wn * 32 + nt * 8 + (lane & 3) * 2;
                *(float2*)(hob + (size_t)o * TLEN + tg) = make_float2(xh0 + xd0, xh1 + xd1);
                flt[mt][nt][hh * 2 + 0] = xh0;
                flt[mt][nt][hh * 2 + 1] = xh1;
            }
        }
    __syncthreads();          // all reads of xdil tiles + P1 done

    // ======== G4: skip = Wk (x) xh ========
    // xh -> (Xh, Xl)
#pragma unroll
    for (int mt = 0; mt < 2; ++mt)
#pragma unroll
        for (int ntp = 0; ntp < 2; ++ntp) {
            uint32_t rh[4], rl[4];
#pragma unroll
            for (int q = 0; q < 4; ++q) {
                float x0 = flt[mt][2 * ntp + (q >> 1)][(q & 1) * 2 + 0];
                float x1 = flt[mt][2 * ntp + (q >> 1)][(q & 1) * 2 + 1];
                uint32_t h = cvt_bf16x2(x1, x0);
                rh[q] = h;
                rl[q] = cvt_bf16x2(x1 - bfhi_f(h), x0 - bflo_f(h));
            }
            uint32_t ad = boff + (uint32_t)ntp * 4096 + sunit[mt];
            STSM4T(Xh + ad, rh);
            STSM4T(Xl + ad, rl);
        }
    init_acc(b_skip + layer * CC);
    CP_WAIT(0);               // mat4 (P0) ready
    __syncthreads();          // xh visible
    mma_mat3(acc, P0h, P0l, Xh, Xl, aoff, boff, lmask, asel, bsel);
#pragma unroll
    for (int mt = 0; mt < 2; ++mt)
#pragma unroll
        for (int nt = 0; nt < 4; ++nt)
#pragma unroll
            for (int hh = 0; hh < 2; ++hh) {
                int o  = wm * 32 + mt * 16 + hh * 8 + (lane >> 2);
                int tg = t0 + wn * 32 + nt * 8 + (lane & 3) * 2;
                *(float2*)(skips + (size_t)o * TLEN + tg) =
                    make_float2(acc[mt][nt][hh * 2 + 0], acc[mt][nt][hh * 2 + 1]);
            }
}

// ---------------- host ----------------
extern "C" void kernel_launch(void* const* d_in, const int* in_sizes, int n_in,
                              void* d_out, int out_size)
{
    const float* x      = (const float*)d_in[0];
    const float* w_in   = (const float*)d_in[1];
    const float* b_in   = (const float*)d_in[2];
    const float* w_dil  = (const float*)d_in[3];
    const float* b_dil  = (const float*)d_in[4];
    const float* w_tanh = (const float*)d_in[5];
    const float* b_tanh = (const float*)d_in[6];
    const float* w_sig  = (const float*)d_in[7];
    const float* b_sig  = (const float*)d_in[8];
    const float* w_skip = (const float*)d_in[9];
    const float* b_skip = (const float*)d_in[10];
    float* out = (float*)d_out;

    cudaFuncSetAttribute(layer_kernel,
                         cudaFuncAttributeMaxDynamicSharedMemorySize, SMEM_TOTAL);

    prep_weights<<<(LL * 5 * CC * CC + 255) / 256, 256>>>(w_dil, w_tanh, w_sig, w_skip);
    input_conv<<<(BB * CC * TLEN / 4 + 255) / 256, 256>>>(x, w_in, b_in);

    const int dils[LL] = {1, 2, 4, 8, 16, 32, 64, 128, 256, 512,
                          1, 2, 4, 8, 16, 32, 64, 128, 256, 512};
    for (int i = 0; i < LL; ++i) {
        layer_kernel<<<(BB * TLEN) / TT, 512, SMEM_TOTAL>>>(
            i, dils[i], i & 1, b_dil, b_tanh, b_sig, b_skip, out);
    }
}

// round 12
// speedup vs baseline: 1.6369x; 1.0881x over previous
#include <cuda_runtime.h>
#include <cuda_bf16.h>
#include <math.h>
#include <stdint.h>

#define CC   128
#define TLEN 8192
#define BB   2
#define LL   20
#define TT   128
#define NTILE (BB * TLEN / TT)   // 128

// smem map (bytes): weight pairs P0/P1 (4 x 32KB) + act tiles X_h, X_l, T3
#define SM_P0H  0
#define SM_P0L  32768
#define SM_P1H  65536
#define SM_P1L  98304
#define SM_XH   131072
#define SM_XL   163840
#define SM_T3   196608
#define SMEM_TOTAL 229376   // 224 KB

// ---------------- device scratch ----------------
__device__ float g_h0[BB * CC * TLEN];
__device__ float g_h1[BB * CC * TLEN];
// weight images: [l][mat 0..4][hl 0..1][16384 bf16], swizzled [o][c] tile layout
__device__ __nv_bfloat16 g_wimg[LL * 5 * 2 * 16384];
// activation image: [ping][tile][hl][16384 bf16] — exact smem tile byte layout
__device__ __nv_bfloat16 g_img[2][NTILE][2][16384];

// ---------------- helpers ----------------
__device__ __forceinline__ uint32_t smem_u32(const void* p) {
    uint32_t a;
    asm("{ .reg .u64 t; cvta.to.shared.u64 t, %1; cvt.u32.u64 %0, t; }" : "=r"(a) : "l"(p));
    return a;
}
// cvt.rn.bf16x2.f32 d, a, b : a -> high half, b -> low half
__device__ __forceinline__ uint32_t cvt_bf16x2(float hi, float lo) {
    uint32_t r; asm("cvt.rn.bf16x2.f32 %0, %1, %2;" : "=r"(r) : "f"(hi), "f"(lo)); return r;
}
__device__ __forceinline__ float bflo_f(uint32_t p) { return __uint_as_float(p << 16); }
__device__ __forceinline__ float bfhi_f(uint32_t p) { return __uint_as_float(p & 0xffff0000u); }

#define LDSM4(r, addr) \
    asm volatile("ldmatrix.sync.aligned.m8n8.x4.shared.b16 {%0,%1,%2,%3}, [%4];" \
        : "=r"((r)[0]), "=r"((r)[1]), "=r"((r)[2]), "=r"((r)[3]) : "r"(addr))
#define LDSM4T(r, addr) \
    asm volatile("ldmatrix.sync.aligned.m8n8.x4.trans.shared.b16 {%0,%1,%2,%3}, [%4];" \
        : "=r"((r)[0]), "=r"((r)[1]), "=r"((r)[2]), "=r"((r)[3]) : "r"(addr))
#define STSM4T(addr, r) \
    asm volatile("stmatrix.sync.aligned.m8n8.x4.trans.shared.b16 [%0], {%1,%2,%3,%4};" \
        :: "r"(addr), "r"((r)[0]), "r"((r)[1]), "r"((r)[2]), "r"((r)[3]))
#define MMA_BF16(d, a, b0, b1) \
    asm volatile("mma.sync.aligned.m16n8k16.row.col.f32.bf16.bf16.f32 " \
        "{%0,%1,%2,%3}, {%4,%5,%6,%7}, {%8,%9}, {%0,%1,%2,%3};" \
        : "+f"((d)[0]), "+f"((d)[1]), "+f"((d)[2]), "+f"((d)[3]) \
        : "r"((a)[0]), "r"((a)[1]), "r"((a)[2]), "r"((a)[3]), "r"(b0), "r"(b1))
#define CP_ASYNC16(saddr, gaddr) \
    asm volatile("cp.async.cg.shared.global [%0], [%1], 16;" :: "r"(saddr), "l"(gaddr))
#define CP_COMMIT() asm volatile("cp.async.commit_group;" ::: "memory")
#define CP_WAIT(n)  asm volatile("cp.async.wait_group %0;" :: "n"(n) : "memory")

// fused tanh(f) * sigmoid(g): 3 MUFU ops
__device__ __forceinline__ float gated(float f, float g) {
    float a  = fabsf(f);
    float ef = __expf(-2.0f * a);
    float eg = __expf(-g);
    float num = copysignf(1.0f - ef, f);
    return __fdividef(num, (1.0f + ef) * (1.0f + eg));
}

// ---------------- prep kernels ----------------
// tile layout byte(r, c) = r*256 + (((c>>3) ^ (r&7))<<4) + (c&7)*2
__global__ void prep_weights(const float* __restrict__ w_dil,
                             const float* __restrict__ w_tanh,
                             const float* __restrict__ w_sig,
                             const float* __restrict__ w_skip)
{
    int idx = blockIdx.x * blockDim.x + threadIdx.x;
    if (idx >= LL * 5 * CC * CC) return;
    int k = idx & 127;
    int o = (idx >> 7) & 127;
    int m = (idx >> 14) % 5;
    int l = idx / (5 * CC * CC);
    size_t oc = ((size_t)l * CC + o) * CC + k;
    float v;
    if (m == 0)      v = w_dil[oc * 2 + 0];
    else if (m == 1) v = w_dil[oc * 2 + 1];
    else if (m == 2) v = w_tanh[oc];
    else if (m == 3) v = w_sig[oc];
    else             v = w_skip[oc];
    __nv_bfloat16 hi = __float2bfloat16(v);
    __nv_bfloat16 lo = __float2bfloat16(v - __bfloat162float(hi));
    uint32_t byte = (uint32_t)o * 256 + ((((uint32_t)(k >> 3)) ^ (o & 7)) << 4) + (k & 7) * 2;
    size_t base = ((size_t)(l * 5 + m) * 2) * 16384;
    g_wimg[base + (byte >> 1)]         = hi;
    g_wimg[base + 16384 + (byte >> 1)] = lo;
}

__global__ void input_conv(const float* __restrict__ x,
                           const float* __restrict__ w_in,
                           const float* __restrict__ b_in)
{
    int i4 = blockIdx.x * blockDim.x + threadIdx.x;
    if (i4 >= BB * CC * TLEN / 4) return;
    int t4 = i4 & (TLEN / 4 - 1);
    int c  = (i4 >> 11) & (CC - 1);
    int b  = i4 >> 18;
    float w = w_in[c], bv = b_in[c];
    float4 xv = ((const float4*)x)[(size_t)b * (TLEN / 4) + t4];
    float4 h;
    h.x = fmaf(w, xv.x, bv); h.y = fmaf(w, xv.y, bv);
    h.z = fmaf(w, xv.z, bv); h.w = fmaf(w, xv.w, bv);
    ((float4*)g_h0)[i4] = h;
}

// build act image (ping 0) from g_h0
__global__ void __launch_bounds__(512, 1) img_build()
{
    const int blk = blockIdx.x;       // tile index
    const int tid = threadIdx.x;
    const int b   = blk >> 6;
    const int t0  = (blk & 63) * TT;
    const int st_t = tid & 127;
    const int quar = tid >> 7;
    const float* src = g_h0 + (size_t)b * CC * TLEN + t0 + st_t;
    const uint32_t rowbase = (uint32_t)st_t * 256;
    const uint32_t rmask   = (uint32_t)(st_t & 7);
    char* ih = (char*)&g_img[0][blk][0][0];
    char* il = (char*)&g_img[0][blk][1][0];
#pragma unroll
    for (int jb = 0; jb < 4; ++jb) {
        int cc0 = quar * 32 + jb * 8;
        uint32_t hreg[4], lreg[4];
#pragma unroll
        for (int e = 0; e < 4; ++e) {
            float v0 = __ldg(src + (size_t)(cc0 + 2 * e) * TLEN);
            float v1 = __ldg(src + (size_t)(cc0 + 2 * e + 1) * TLEN);
            uint32_t h2 = cvt_bf16x2(v1, v0);
            hreg[e] = h2;
            lreg[e] = cvt_bf16x2(v1 - bfhi_f(h2), v0 - bflo_f(h2));
        }
        uint32_t off = rowbase + ((((uint32_t)(cc0 >> 3)) ^ rmask) << 4);
        *(uint4*)(ih + off) = make_uint4(hreg[0], hreg[1], hreg[2], hreg[3]);
        *(uint4*)(il + off) = make_uint4(lreg[0], lreg[1], lreg[2], lreg[3]);
    }
}

// ---------------- fused 3-term matrix pass ----------------
__device__ __forceinline__ void mma_mat3(float (&acc)[2][4][4],
                                         uint32_t wHi, uint32_t wLo,
                                         uint32_t xH, uint32_t xL,
                                         uint32_t aoff, uint32_t boff,
                                         uint32_t lmask, uint32_t asel, uint32_t bsel)
{
#pragma unroll
    for (int ks = 0; ks < 8; ++ks) {
        uint32_t acu = (((uint32_t)(2 * ks) + asel) << 4) ^ lmask;
        uint32_t ah0[4], ah1[4], al0[4], al1[4];
        LDSM4(ah0, wHi + aoff + acu);
        LDSM4(ah1, wHi + aoff + 4096 + acu);
        LDSM4(al0, wLo + aoff + acu);
        LDSM4(al1, wLo + aoff + 4096 + acu);
        uint32_t bcu = (((uint32_t)(2 * ks) + bsel) << 4) ^ lmask;
#pragma unroll
        for (int ntp = 0; ntp < 2; ++ntp) {
            uint32_t bh[4], bl[4];
            LDSM4(bh, xH + boff + (uint32_t)ntp * 4096 + bcu);
            LDSM4(bl, xL + boff + (uint32_t)ntp * 4096 + bcu);
            MMA_BF16(acc[0][2 * ntp],     ah0, bh[0], bh[1]);
            MMA_BF16(acc[0][2 * ntp + 1], ah0, bh[2], bh[3]);
            MMA_BF16(acc[1][2 * ntp],     ah1, bh[0], bh[1]);
            MMA_BF16(acc[1][2 * ntp + 1], ah1, bh[2], bh[3]);
            MMA_BF16(acc[0][2 * ntp],     ah0, bl[0], bl[1]);
            MMA_BF16(acc[0][2 * ntp + 1], ah0, bl[2], bl[3]);
            MMA_BF16(acc[1][2 * ntp],     ah1, bl[0], bl[1]);
            MMA_BF16(acc[1][2 * ntp + 1], ah1, bl[2], bl[3]);
            MMA_BF16(acc[0][2 * ntp],     al0, bh[0], bh[1]);
            MMA_BF16(acc[0][2 * ntp + 1], al0, bh[2], bh[3]);
            MMA_BF16(acc[1][2 * ntp],     al1, bh[0], bh[1]);
            MMA_BF16(acc[1][2 * ntp + 1], al1, bh[2], bh[3]);
        }
    }
}

// ---------------- fused layer kernel ----------------
__global__ void __launch_bounds__(512, 1)
layer_kernel(int layer, int dil, int ping,
             const float* __restrict__ b_dil, const float* __restrict__ b_tanh,
             const float* __restrict__ b_sig, const float* __restrict__ b_skip,
             float* __restrict__ out_base)
{
    extern __shared__ char smem[];
    const uint32_t sb = smem_u32(smem);
    const int tid = threadIdx.x;
    const int wid = tid >> 5, lane = tid & 31;
    const int wm = wid & 3, wn = wid >> 2;

    const float* hin  = ping ? g_h1 : g_h0;
    float*       hout = ping ? g_h0 : g_h1;
    const int blk = blockIdx.x;
    const int b   = blk >> 6;
    const int t0  = (blk & 63) * TT;
    const float* hbase = hin + (size_t)b * CC * TLEN;
    float* hob     = hout + (size_t)b * CC * TLEN;
    float* outputs = out_base + ((size_t)layer * BB + b) * CC * TLEN;
    float* skips   = out_base + (size_t)LL * BB * CC * TLEN + ((size_t)layer * BB + b) * CC * TLEN;

    auto prefetch_mat = [&](int m, int p) {
        const char* gh = (const char*)(g_wimg + ((size_t)(layer * 5 + m) * 2 + 0) * 16384);
        const char* gl = (const char*)(g_wimg + ((size_t)(layer * 5 + m) * 2 + 1) * 16384);
        uint32_t dh = sb + (p ? SM_P1H : SM_P0H);
        uint32_t dl = sb + (p ? SM_P1L : SM_P0L);
#pragma unroll
        for (int j = 0; j < 4; ++j)
            CP_ASYNC16(dh + tid * 16 + j * 8192, gh + tid * 16 + j * 8192);
#pragma unroll
        for (int j = 0; j < 4; ++j)
            CP_ASYNC16(dl + tid * 16 + j * 8192, gl + tid * 16 + j * 8192);
        CP_COMMIT();
    };

    // ---- staging constants
    const int st_t = tid & 127;
    const int quar = tid >> 7;
    const uint32_t rowbase = (uint32_t)st_t * 256;
    const uint32_t rmask   = (uint32_t)(st_t & 7);

    // fp32 staging (hdel only)
    auto stage = [&](const float* src, bool valid, uint32_t dsth, uint32_t dstl) {
#pragma unroll
        for (int jb = 0; jb < 4; ++jb) {
            int cc0 = quar * 32 + jb * 8;
            uint32_t hreg[4], lreg[4];
#pragma unroll
            for (int e = 0; e < 4; ++e) {
                float v0 = valid ? __ldg(src + (size_t)(cc0 + 2 * e) * TLEN) : 0.0f;
                float v1 = valid ? __ldg(src + (size_t)(cc0 + 2 * e + 1) * TLEN) : 0.0f;
                uint32_t h2 = cvt_bf16x2(v1, v0);
                hreg[e] = h2;
                lreg[e] = cvt_bf16x2(v1 - bfhi_f(h2), v0 - bflo_f(h2));
            }
            uint32_t unit = (((uint32_t)(cc0 >> 3)) ^ rmask) << 4;
            *(uint4*)(smem + (dsth - sb) + rowbase + unit) =
                make_uint4(hreg[0], hreg[1], hreg[2], hreg[3]);
            *(uint4*)(smem + (dstl - sb) + rowbase + unit) =
                make_uint4(lreg[0], lreg[1], lreg[2], lreg[3]);
        }
    };

    // per-lane MMA invariants
    const uint32_t lmask = (uint32_t)(lane & 7) << 4;
    const uint32_t asel = (uint32_t)((lane >> 4) & 1);
    const uint32_t bsel = (uint32_t)((lane >> 3) & 1);
    const uint32_t aoff = (uint32_t)(wm * 32 + (lane & 7) + ((lane >> 3) & 1) * 8) * 256;
    const uint32_t boff = (uint32_t)(wn * 32 + (lane & 7) + ((lane >> 4) & 1) * 8) * 256;
    uint32_t sunit[2];
#pragma unroll
    for (int mt = 0; mt < 2; ++mt)
        sunit[mt] = (((uint32_t)(wm * 4 + mt * 2 + ((lane >> 3) & 1))) << 4) ^ lmask;

    const uint32_t P0h = sb + SM_P0H, P0l = sb + SM_P0L;
    const uint32_t P1h = sb + SM_P1H, P1l = sb + SM_P1L;
    const uint32_t Xh = sb + SM_XH, Xl = sb + SM_XL, T3 = sb + SM_T3;

    float acc[2][4][4];
    float flt[2][4][4];

    auto init_acc = [&](const float* bias) {
#pragma unroll
        for (int mt = 0; mt < 2; ++mt) {
            float v0 = __ldg(bias + wm * 32 + mt * 16 + (lane >> 2));
            float v1 = __ldg(bias + wm * 32 + mt * 16 + 8 + (lane >> 2));
#pragma unroll
            for (int nt = 0; nt < 4; ++nt) {
                acc[mt][nt][0] = v0; acc[mt][nt][1] = v0;
                acc[mt][nt][2] = v1; acc[mt][nt][3] = v1;
            }
        }
    };

    // ======== C1: cp.async hcur image -> Xh, Xl ========
    {
        const char* gih = (const char*)&g_img[ping][blk][0][0];
        const char* gil = (const char*)&g_img[ping][blk][1][0];
#pragma unroll
        for (int j = 0; j < 4; ++j)
            CP_ASYNC16(Xh + tid * 16 + j * 8192, gih + tid * 16 + j * 8192);
#pragma unroll
        for (int j = 0; j < 4; ++j)
            CP_ASYNC16(Xl + tid * 16 + j * 8192, gil + tid * 16 + j * 8192);
        CP_COMMIT();
    }
    prefetch_mat(1, 0);   // C2: w_dil tap-1 -> P0
    prefetch_mat(0, 1);   // C3: w_dil tap-0 -> P1

    init_acc(b_dil + layer * CC);

    // ======== G1a: acc += W1 (x) hcur ========
    CP_WAIT(1);               // C1 (img) + C2 (mat1) done
    __syncthreads();
    mma_mat3(acc, P0h, P0l, Xh, Xl, aoff, boff, lmask, asel, bsel);

    // ---- outputs copy: reconstruct fp32 h from smem tiles (tiles read-only here)
    {
        float* outp = outputs + t0 + st_t;
#pragma unroll
        for (int jb = 0; jb < 4; ++jb) {
            int cc0 = quar * 32 + jb * 8;
            uint32_t off = rowbase + ((((uint32_t)(cc0 >> 3)) ^ rmask) << 4);
            uint4 hv = *(const uint4*)(smem + SM_XH + off);
            uint4 lv = *(const uint4*)(smem + SM_XL + off);
            uint32_t he[4] = {hv.x, hv.y, hv.z, hv.w};
            uint32_t le[4] = {lv.x, lv.y, lv.z, lv.w};
#pragma unroll
            for (int e = 0; e < 4; ++e) {
                outp[(size_t)(cc0 + 2 * e) * TLEN]     = bflo_f(he[e]) + bflo_f(le[e]);
                outp[(size_t)(cc0 + 2 * e + 1) * TLEN] = bfhi_f(he[e]) + bfhi_f(le[e]);
            }
        }
    }
    __syncthreads();          // P0 + X tiles free

    // ======== G1b: acc += W0 (x) hdel ========
    prefetch_mat(2, 0);       // C4: w_tanh -> P0
    stage(hbase + t0 + st_t - dil, (t0 + st_t - dil) >= 0, T3, Xl);
    CP_WAIT(1);               // C3 (mat0) done
    __syncthreads();
    mma_mat3(acc, P1h, P1l, T3, Xl, aoff, boff, lmask, asel, bsel);
    __syncthreads();

    // ======== epi1: xdil -> (Xh, Xl) ========
    prefetch_mat(3, 1);       // C5: w_sig -> P1
#pragma unroll
    for (int mt = 0; mt < 2; ++mt)
#pragma unroll
        for (int ntp = 0; ntp < 2; ++ntp) {
            uint32_t rh[4], rl[4];
#pragma unroll
            for (int q = 0; q < 4; ++q) {
                float d0 = acc[mt][2 * ntp + (q >> 1)][(q & 1) * 2 + 0];
                float d1 = acc[mt][2 * ntp + (q >> 1)][(q & 1) * 2 + 1];
                uint32_t h = cvt_bf16x2(d1, d0);
                rh[q] = h;
                rl[q] = cvt_bf16x2(d1 - bfhi_f(h), d0 - bflo_f(h));
            }
            uint32_t ad = boff + (uint32_t)ntp * 4096 + sunit[mt];
            STSM4T(Xh + ad, rh);
            STSM4T(Xl + ad, rl);
        }
    CP_WAIT(1);               // C4 (w_tanh) done
    __syncthreads();

    // ======== G2: raw filt pre-activation kept in regs ========
    init_acc(b_tanh + layer * CC);
    mma_mat3(acc, P0h, P0l, Xh, Xl, aoff, boff, lmask, asel, bsel);
#pragma unroll
    for (int mt = 0; mt < 2; ++mt)
#pragma unroll
        for (int nt = 0; nt < 4; ++nt)
#pragma unroll
            for (int q = 0; q < 4; ++q)
                flt[mt][nt][q] = acc[mt][nt][q];
    __syncthreads();          // P0 free

    // ======== G3: gate; h_next -> global fp32 + image; xh into flt ========
    prefetch_mat(4, 0);       // C6: w_skip -> P0
    init_acc(b_sig + layer * CC);
    CP_WAIT(1);               // C5 (w_sig) done
    __syncthreads();
    mma_mat3(acc, P1h, P1l, Xh, Xl, aoff, boff, lmask, asel, bsel);
    __syncthreads();          // ALL warps done with P1 weights (P1h reused below)
#pragma unroll
    for (int mt = 0; mt < 2; ++mt)
#pragma unroll
        for (int ntp = 0; ntp < 2; ++ntp) {
            uint32_t ad = boff + (uint32_t)ntp * 4096 + sunit[mt];
            uint32_t xdh[4], xdl[4];
            LDSM4T(xdh, Xh + ad);
            LDSM4T(xdl, Xl + ad);
            uint32_t hnh[4], hnl[4];
#pragma unroll
            for (int q = 0; q < 4; ++q) {
                int nt = 2 * ntp + (q >> 1), hh = q & 1;
                float xd0 = bflo_f(xdh[q]) + bflo_f(xdl[q]);
                float xd1 = bfhi_f(xdh[q]) + bfhi_f(xdl[q]);
                float xh0 = gated(flt[mt][nt][hh * 2 + 0], acc[mt][nt][hh * 2 + 0]);
                float xh1 = gated(flt[mt][nt][hh * 2 + 1], acc[mt][nt][hh * 2 + 1]);
                float hn0 = xh0 + xd0, hn1 = xh1 + xd1;
                int o  = wm * 32 + mt * 16 + hh * 8 + (lane >> 2);
                int tg = t0 + wn * 32 + nt * 8 + (lane & 3) * 2;
                *(float2*)(hob + (size_t)o * TLEN + tg) = make_float2(hn0, hn1);
                flt[mt][nt][hh * 2 + 0] = xh0;
                flt[mt][nt][hh * 2 + 1] = xh1;
                uint32_t h2 = cvt_bf16x2(hn1, hn0);
                hnh[q] = h2;
                hnl[q] = cvt_bf16x2(hn1 - bfhi_f(h2), hn0 - bflo_f(h2));
            }
            STSM4T(T3 + ad, hnh);     // h_next hi image tile
            STSM4T(P1h + ad, hnl);    // h_next lo image tile (P1 free)
        }
    __syncthreads();

    // ======== copy h_next image -> global; stage xh -> (Xh, Xl) ========
    {
        char* oih = (char*)&g_img[1 - ping][blk][0][0];
        char* oil = (char*)&g_img[1 - ping][blk][1][0];
#pragma unroll
        for (int j = 0; j < 4; ++j)
            *(uint4*)(oih + tid * 16 + j * 8192) = *(const uint4*)(smem + SM_T3 + tid * 16 + j * 8192);
#pragma unroll
        for (int j = 0; j < 4; ++j)
            *(uint4*)(oil + tid * 16 + j * 8192) = *(const uint4*)(smem + SM_P1H + tid * 16 + j * 8192);
    }
#pragma unroll
    for (int mt = 0; mt < 2; ++mt)
#pragma unroll
        for (int ntp = 0; ntp < 2; ++ntp) {
            uint32_t rh[4], rl[4];
#pragma unroll
            for (int q = 0; q < 4; ++q) {
                float x0 = flt[mt][2 * ntp + (q >> 1)][(q & 1) * 2 + 0];
                float x1 = flt[mt][2 * ntp + (q >> 1)][(q & 1) * 2 + 1];
                uint32_t h = cvt_bf16x2(x1, x0);
                rh[q] = h;
                rl[q] = cvt_bf16x2(x1 - bfhi_f(h), x0 - bflo_f(h));
            }
            uint32_t ad = boff + (uint32_t)ntp * 4096 + sunit[mt];
            STSM4T(Xh + ad, rh);
            STSM4T(Xl + ad, rl);
        }
    init_acc(b_skip + layer * CC);
    CP_WAIT(0);               // C6 (w_skip) done
    __syncthreads();

    // ======== G4: skip = Wk (x) xh ========
    mma_mat3(acc, P0h, P0l, Xh, Xl, aoff, boff, lmask, asel, bsel);
#pragma unroll
    for (int mt = 0; mt < 2; ++mt)
#pragma unroll
        for (int nt = 0; nt < 4; ++nt)
#pragma unroll
            for (int hh = 0; hh < 2; ++hh) {
                int o  = wm * 32 + mt * 16 + hh * 8 + (lane >> 2);
                int tg = t0 + wn * 32 + nt * 8 + (lane & 3) * 2;
                *(float2*)(skips + (size_t)o * TLEN + tg) =
                    make_float2(acc[mt][nt][hh * 2 + 0], acc[mt][nt][hh * 2 + 1]);
            }
}

// ---------------- host ----------------
extern "C" void kernel_launch(void* const* d_in, const int* in_sizes, int n_in,
                              void* d_out, int out_size)
{
    const float* x      = (const float*)d_in[0];
    const float* w_in   = (const float*)d_in[1];
    const float* b_in   = (const float*)d_in[2];
    const float* w_dil  = (const float*)d_in[3];
    const float* b_dil  = (const float*)d_in[4];
    const float* w_tanh = (const float*)d_in[5];
    const float* b_tanh = (const float*)d_in[6];
    const float* w_sig  = (const float*)d_in[7];
    const float* b_sig  = (const float*)d_in[8];
    const float* w_skip = (const float*)d_in[9];
    const float* b_skip = (const float*)d_in[10];
    float* out = (float*)d_out;

    cudaFuncSetAttribute(layer_kernel,
                         cudaFuncAttributeMaxDynamicSharedMemorySize, SMEM_TOTAL);

    prep_weights<<<(LL * 5 * CC * CC + 255) / 256, 256>>>(w_dil, w_tanh, w_sig, w_skip);
    input_conv<<<(BB * CC * TLEN / 4 + 255) / 256, 256>>>(x, w_in, b_in);
    img_build<<<NTILE, 512>>>();

    const int dils[LL] = {1, 2, 4, 8, 16, 32, 64, 128, 256, 512,
                          1, 2, 4, 8, 16, 32, 64, 128, 256, 512};
    for (int i = 0; i < LL; ++i) {
        layer_kernel<<<(BB * TLEN) / TT, 512, SMEM_TOTAL>>>(
            i, dils[i], i & 1, b_dil, b_tanh, b_sig, b_skip, out);
    }
}

// round 13
// speedup vs baseline: 1.6455x; 1.0053x over previous
#include <cuda_runtime.h>
#include <cuda_bf16.h>
#include <math.h>
#include <stdint.h>

#define CC   128
#define TLEN 8192
#define BB   2
#define LL   20
#define TT   128
#define NTILE (BB * TLEN / TT)   // 128

// smem: 7 x 32KB rotating buffers
#define SMB(i) ((uint32_t)(i) * 32768u)
#define SMEM_TOTAL (7 * 32768)

// ---------------- device scratch ----------------
__device__ float g_h0[BB * CC * TLEN];
// weight images: [l][mat 0..4][hl 0..1][16384 bf16], swizzled [o][c] tile layout
__device__ __nv_bfloat16 g_wimg[LL * 5 * 2 * 16384];
// activation image: [ping][tile][hl][16384 bf16] — exact smem tile byte layout
__device__ __nv_bfloat16 g_img[2][NTILE][2][16384];
__device__ __nv_bfloat16 g_zero[8];   // 16B zero page (zero-initialized)

// ---------------- helpers ----------------
__device__ __forceinline__ uint32_t smem_u32(const void* p) {
    uint32_t a;
    asm("{ .reg .u64 t; cvta.to.shared.u64 t, %1; cvt.u32.u64 %0, t; }" : "=r"(a) : "l"(p));
    return a;
}
__device__ __forceinline__ uint32_t cvt_bf16x2(float hi, float lo) {
    uint32_t r; asm("cvt.rn.bf16x2.f32 %0, %1, %2;" : "=r"(r) : "f"(hi), "f"(lo)); return r;
}
__device__ __forceinline__ float bflo_f(uint32_t p) { return __uint_as_float(p << 16); }
__device__ __forceinline__ float bfhi_f(uint32_t p) { return __uint_as_float(p & 0xffff0000u); }

#define LDSM4(r, addr) \
    asm volatile("ldmatrix.sync.aligned.m8n8.x4.shared.b16 {%0,%1,%2,%3}, [%4];" \
        : "=r"((r)[0]), "=r"((r)[1]), "=r"((r)[2]), "=r"((r)[3]) : "r"(addr))
#define LDSM4T(r, addr) \
    asm volatile("ldmatrix.sync.aligned.m8n8.x4.trans.shared.b16 {%0,%1,%2,%3}, [%4];" \
        : "=r"((r)[0]), "=r"((r)[1]), "=r"((r)[2]), "=r"((r)[3]) : "r"(addr))
#define STSM4T(addr, r) \
    asm volatile("stmatrix.sync.aligned.m8n8.x4.trans.shared.b16 [%0], {%1,%2,%3,%4};" \
        :: "r"(addr), "r"((r)[0]), "r"((r)[1]), "r"((r)[2]), "r"((r)[3]))
#define MMA_BF16(d, a, b0, b1) \
    asm volatile("mma.sync.aligned.m16n8k16.row.col.f32.bf16.bf16.f32 " \
        "{%0,%1,%2,%3}, {%4,%5,%6,%7}, {%8,%9}, {%0,%1,%2,%3};" \
        : "+f"((d)[0]), "+f"((d)[1]), "+f"((d)[2]), "+f"((d)[3]) \
        : "r"((a)[0]), "r"((a)[1]), "r"((a)[2]), "r"((a)[3]), "r"(b0), "r"(b1))
#define CP_ASYNC16(saddr, gaddr) \
    asm volatile("cp.async.cg.shared.global [%0], [%1], 16;" :: "r"(saddr), "l"(gaddr))
#define CP_COMMIT() asm volatile("cp.async.commit_group;" ::: "memory")
#define CP_WAIT(n)  asm volatile("cp.async.wait_group %0;" :: "n"(n) : "memory")

// fused tanh(f) * sigmoid(g): 3 MUFU ops
__device__ __forceinline__ float gated(float f, float g) {
    float a  = fabsf(f);
    float ef = __expf(-2.0f * a);
    float eg = __expf(-g);
    float num = copysignf(1.0f - ef, f);
    return __fdividef(num, (1.0f + ef) * (1.0f + eg));
}

// ---------------- prep kernels ----------------
__global__ void prep_weights(const float* __restrict__ w_dil,
                             const float* __restrict__ w_tanh,
                             const float* __restrict__ w_sig,
                             const float* __restrict__ w_skip)
{
    int idx = blockIdx.x * blockDim.x + threadIdx.x;
    if (idx >= LL * 5 * CC * CC) return;
    int k = idx & 127;
    int o = (idx >> 7) & 127;
    int m = (idx >> 14) % 5;
    int l = idx / (5 * CC * CC);
    size_t oc = ((size_t)l * CC + o) * CC + k;
    float v;
    if (m == 0)      v = w_dil[oc * 2 + 0];
    else if (m == 1) v = w_dil[oc * 2 + 1];
    else if (m == 2) v = w_tanh[oc];
    else if (m == 3) v = w_sig[oc];
    else             v = w_skip[oc];
    __nv_bfloat16 hi = __float2bfloat16(v);
    __nv_bfloat16 lo = __float2bfloat16(v - __bfloat162float(hi));
    uint32_t byte = (uint32_t)o * 256 + ((((uint32_t)(k >> 3)) ^ (o & 7)) << 4) + (k & 7) * 2;
    size_t base = ((size_t)(l * 5 + m) * 2) * 16384;
    g_wimg[base + (byte >> 1)]         = hi;
    g_wimg[base + 16384 + (byte >> 1)] = lo;
}

__global__ void input_conv(const float* __restrict__ x,
                           const float* __restrict__ w_in,
                           const float* __restrict__ b_in)
{
    int i4 = blockIdx.x * blockDim.x + threadIdx.x;
    if (i4 >= BB * CC * TLEN / 4) return;
    int t4 = i4 & (TLEN / 4 - 1);
    int c  = (i4 >> 11) & (CC - 1);
    int b  = i4 >> 18;
    float w = w_in[c], bv = b_in[c];
    float4 xv = ((const float4*)x)[(size_t)b * (TLEN / 4) + t4];
    float4 h;
    h.x = fmaf(w, xv.x, bv); h.y = fmaf(w, xv.y, bv);
    h.z = fmaf(w, xv.z, bv); h.w = fmaf(w, xv.w, bv);
    ((float4*)g_h0)[i4] = h;
}

// build act image (ping 0) from g_h0
__global__ void __launch_bounds__(512, 1) img_build()
{
    const int blk = blockIdx.x;
    const int tid = threadIdx.x;
    const int b   = blk >> 6;
    const int t0  = (blk & 63) * TT;
    const int st_t = tid & 127;
    const int quar = tid >> 7;
    const float* src = g_h0 + (size_t)b * CC * TLEN + t0 + st_t;
    const uint32_t rowbase = (uint32_t)st_t * 256;
    const uint32_t rmask   = (uint32_t)(st_t & 7);
    char* ih = (char*)&g_img[0][blk][0][0];
    char* il = (char*)&g_img[0][blk][1][0];
#pragma unroll
    for (int jb = 0; jb < 4; ++jb) {
        int cc0 = quar * 32 + jb * 8;
        uint32_t hreg[4], lreg[4];
#pragma unroll
        for (int e = 0; e < 4; ++e) {
            float v0 = __ldg(src + (size_t)(cc0 + 2 * e) * TLEN);
            float v1 = __ldg(src + (size_t)(cc0 + 2 * e + 1) * TLEN);
            uint32_t h2 = cvt_bf16x2(v1, v0);
            hreg[e] = h2;
            lreg[e] = cvt_bf16x2(v1 - bfhi_f(h2), v0 - bflo_f(h2));
        }
        uint32_t off = rowbase + ((((uint32_t)(cc0 >> 3)) ^ rmask) << 4);
        *(uint4*)(ih + off) = make_uint4(hreg[0], hreg[1], hreg[2], hreg[3]);
        *(uint4*)(il + off) = make_uint4(lreg[0], lreg[1], lreg[2], lreg[3]);
    }
}

// ---------------- fused 3-term matrix pass ----------------
__device__ __forceinline__ void mma_mat3(float (&acc)[2][4][4],
                                         uint32_t wHi, uint32_t wLo,
                                         uint32_t xH, uint32_t xL,
                                         uint32_t aoff, uint32_t boff,
                                         uint32_t lmask, uint32_t asel, uint32_t bsel)
{
#pragma unroll
    for (int ks = 0; ks < 8; ++ks) {
        uint32_t acu = (((uint32_t)(2 * ks) + asel) << 4) ^ lmask;
        uint32_t ah0[4], ah1[4], al0[4], al1[4];
        LDSM4(ah0, wHi + aoff + acu);
        LDSM4(ah1, wHi + aoff + 4096 + acu);
        LDSM4(al0, wLo + aoff + acu);
        LDSM4(al1, wLo + aoff + 4096 + acu);
        uint32_t bcu = (((uint32_t)(2 * ks) + bsel) << 4) ^ lmask;
#pragma unroll
        for (int ntp = 0; ntp < 2; ++ntp) {
            uint32_t bh[4], bl[4];
            LDSM4(bh, xH + boff + (uint32_t)ntp * 4096 + bcu);
            LDSM4(bl, xL + boff + (uint32_t)ntp * 4096 + bcu);
            MMA_BF16(acc[0][2 * ntp],     ah0, bh[0], bh[1]);
            MMA_BF16(acc[0][2 * ntp + 1], ah0, bh[2], bh[3]);
            MMA_BF16(acc[1][2 * ntp],     ah1, bh[0], bh[1]);
            MMA_BF16(acc[1][2 * ntp + 1], ah1, bh[2], bh[3]);
            MMA_BF16(acc[0][2 * ntp],     ah0, bl[0], bl[1]);
            MMA_BF16(acc[0][2 * ntp + 1], ah0, bl[2], bl[3]);
            MMA_BF16(acc[1][2 * ntp],     ah1, bl[0], bl[1]);
            MMA_BF16(acc[1][2 * ntp + 1], ah1, bl[2], bl[3]);
            MMA_BF16(acc[0][2 * ntp],     al0, bh[0], bh[1]);
            MMA_BF16(acc[0][2 * ntp + 1], al0, bh[2], bh[3]);
            MMA_BF16(acc[1][2 * ntp],     al1, bh[0], bh[1]);
            MMA_BF16(acc[1][2 * ntp + 1], al1, bh[2], bh[3]);
        }
    }
}

// ---------------- fused layer kernel ----------------
__global__ void __launch_bounds__(512, 1)
layer_kernel(int layer, int dil, int ping,
             const float* __restrict__ b_dil, const float* __restrict__ b_tanh,
             const float* __restrict__ b_sig, const float* __restrict__ b_skip,
             float* __restrict__ out_base)
{
    extern __shared__ char smem[];
    const uint32_t sb = smem_u32(smem);
    const int tid = threadIdx.x;
    const int wid = tid >> 5, lane = tid & 31;
    const int wm = wid & 3, wn = wid >> 2;

    const int blk = blockIdx.x;
    const int b   = blk >> 6;
    const int t0  = (blk & 63) * TT;
    float* outputs = out_base + ((size_t)layer * BB + b) * CC * TLEN;
    float* skips   = out_base + (size_t)LL * BB * CC * TLEN + ((size_t)layer * BB + b) * CC * TLEN;

    const uint32_t B0 = sb + SMB(0), B1 = sb + SMB(1), B2 = sb + SMB(2),
                   B3 = sb + SMB(3), B4 = sb + SMB(4), B5 = sb + SMB(5),
                   B6 = sb + SMB(6);

    auto prefetch_mat = [&](int m, uint32_t dh, uint32_t dl) {
        const char* gh = (const char*)(g_wimg + ((size_t)(layer * 5 + m) * 2 + 0) * 16384);
        const char* gl = (const char*)(g_wimg + ((size_t)(layer * 5 + m) * 2 + 1) * 16384);
#pragma unroll
        for (int j = 0; j < 4; ++j)
            CP_ASYNC16(dh + tid * 16 + j * 8192, gh + tid * 16 + j * 8192);
#pragma unroll
        for (int j = 0; j < 4; ++j)
            CP_ASYNC16(dl + tid * 16 + j * 8192, gl + tid * 16 + j * 8192);
        CP_COMMIT();
    };

    // hdel plane copy: swizzle-remapped cp.async from previous-layer image
    auto hdel_cp = [&](int pl, uint32_t dstbase) {
#pragma unroll
        for (int j = 0; j < 4; ++j) {
            int u = tid * 4 + j;
            int row = u >> 4, cu = u & 15;
            int sg = t0 + row - dil;
            const char* src;
            if (sg >= 0) {
                int stile = b * 64 + (sg >> 7);
                int srow  = sg & 127;
                int scu   = cu ^ ((row ^ srow) & 7);
                src = (const char*)&g_img[ping][stile][pl][0] + srow * 256 + scu * 16;
            } else {
                src = (const char*)g_zero;
            }
            CP_ASYNC16(dstbase + (uint32_t)u * 16, src);
        }
    };

    // ---- staging constants (outputs reconstruct)
    const int st_t = tid & 127;
    const int quar = tid >> 7;
    const uint32_t rowbase = (uint32_t)st_t * 256;
    const uint32_t rmask   = (uint32_t)(st_t & 7);

    // per-lane MMA invariants
    const uint32_t lmask = (uint32_t)(lane & 7) << 4;
    const uint32_t asel = (uint32_t)((lane >> 4) & 1);
    const uint32_t bsel = (uint32_t)((lane >> 3) & 1);
    const uint32_t aoff = (uint32_t)(wm * 32 + (lane & 7) + ((lane >> 3) & 1) * 8) * 256;
    const uint32_t boff = (uint32_t)(wn * 32 + (lane & 7) + ((lane >> 4) & 1) * 8) * 256;
    uint32_t sunit[2];
#pragma unroll
    for (int mt = 0; mt < 2; ++mt)
        sunit[mt] = (((uint32_t)(wm * 4 + mt * 2 + ((lane >> 3) & 1))) << 4) ^ lmask;

    float acc[2][4][4];
    float flt[2][4][4];

    auto init_acc = [&](const float* bias) {
#pragma unroll
        for (int mt = 0; mt < 2; ++mt) {
            float v0 = __ldg(bias + wm * 32 + mt * 16 + (lane >> 2));
            float v1 = __ldg(bias + wm * 32 + mt * 16 + 8 + (lane >> 2));
#pragma unroll
            for (int nt = 0; nt < 4; ++nt) {
                acc[mt][nt][0] = v0; acc[mt][nt][1] = v0;
                acc[mt][nt][2] = v1; acc[mt][nt][3] = v1;
            }
        }
    };

    // ======== C0: hcur image -> B4,B5 ; hdel-hi -> B6 ========
    {
        const char* gih = (const char*)&g_img[ping][blk][0][0];
        const char* gil = (const char*)&g_img[ping][blk][1][0];
#pragma unroll
        for (int j = 0; j < 4; ++j)
            CP_ASYNC16(B4 + tid * 16 + j * 8192, gih + tid * 16 + j * 8192);
#pragma unroll
        for (int j = 0; j < 4; ++j)
            CP_ASYNC16(B5 + tid * 16 + j * 8192, gil + tid * 16 + j * 8192);
        hdel_cp(0, B6);
        CP_COMMIT();
    }
    prefetch_mat(1, B0, B1);   // C1: w_dil tap-1
    prefetch_mat(0, B2, B3);   // C2: w_dil tap-0

    init_acc(b_dil + layer * CC);

    // ======== G1a: acc += W1 (x) hcur ========
    CP_WAIT(1);                // C0 + C1 done (C2 may fly)
    __syncthreads();
    mma_mat3(acc, B0, B1, B4, B5, aoff, boff, lmask, asel, bsel);

    // ---- outputs copy: reconstruct fp32 h from hcur tiles
    {
        float* outp = outputs + t0 + st_t;
#pragma unroll
        for (int jb = 0; jb < 4; ++jb) {
            int cc0 = quar * 32 + jb * 8;
            uint32_t off = rowbase + ((((uint32_t)(cc0 >> 3)) ^ rmask) << 4);
            uint4 hv = *(const uint4*)(smem + SMB(4) + off);
            uint4 lv = *(const uint4*)(smem + SMB(5) + off);
            uint32_t he[4] = {hv.x, hv.y, hv.z, hv.w};
            uint32_t le[4] = {lv.x, lv.y, lv.z, lv.w};
#pragma unroll
            for (int e = 0; e < 4; ++e) {
                outp[(size_t)(cc0 + 2 * e) * TLEN]     = bflo_f(he[e]) + bflo_f(le[e]);
                outp[(size_t)(cc0 + 2 * e + 1) * TLEN] = bfhi_f(he[e]) + bfhi_f(le[e]);
            }
        }
    }
    __syncthreads();           // B0,B1,B4,B5 free

    // ======== G1b: acc += W0 (x) hdel ========
    hdel_cp(1, B4); CP_COMMIT();   // C3: hdel-lo -> B4
    prefetch_mat(2, B0, B1);       // C4: w_tanh
    CP_WAIT(1);                    // C2 + C3 done (C4 may fly)
    __syncthreads();
    mma_mat3(acc, B2, B3, B6, B4, aoff, boff, lmask, asel, bsel);
    __syncthreads();           // B2,B3,B4,B6 free

    // ======== epi1: xdil -> (B2,B3) ========
    prefetch_mat(3, B5, B6);       // C5: w_sig
#pragma unroll
    for (int mt = 0; mt < 2; ++mt)
#pragma unroll
        for (int ntp = 0; ntp < 2; ++ntp) {
            uint32_t rh[4], rl[4];
#pragma unroll
            for (int q = 0; q < 4; ++q) {
                float d0 = acc[mt][2 * ntp + (q >> 1)][(q & 1) * 2 + 0];
                float d1 = acc[mt][2 * ntp + (q >> 1)][(q & 1) * 2 + 1];
                uint32_t h = cvt_bf16x2(d1, d0);
                rh[q] = h;
                rl[q] = cvt_bf16x2(d1 - bfhi_f(h), d0 - bflo_f(h));
            }
            uint32_t ad = boff + (uint32_t)ntp * 4096 + sunit[mt];
            STSM4T(B2 + ad, rh);
            STSM4T(B3 + ad, rl);
        }
    CP_WAIT(1);                // C4 (w_tanh) done (C5 may fly)
    __syncthreads();           // xdil visible

    // ======== G2: filt pre-activation kept in regs ========
    init_acc(b_tanh + layer * CC);
    mma_mat3(acc, B0, B1, B2, B3, aoff, boff, lmask, asel, bsel);
#pragma unroll
    for (int mt = 0; mt < 2; ++mt)
#pragma unroll
        for (int nt = 0; nt < 4; ++nt)
#pragma unroll
            for (int q = 0; q < 4; ++q)
                flt[mt][nt][q] = acc[mt][nt][q];
    __syncthreads();           // B0,B1 free

    // ======== G3: gate ========
    prefetch_mat(4, B0, B1);       // C6: w_skip
    init_acc(b_sig + layer * CC);
    CP_WAIT(1);                // C5 (w_sig) done (C6 may fly)
    __syncthreads();
    mma_mat3(acc, B5, B6, B2, B3, aoff, boff, lmask, asel, bsel);
    __syncthreads();           // B5,B6 free

    // ======== epi3: gated; h_next image -> (B5,B6); xh -> (B2,B3) ========
#pragma unroll
    for (int mt = 0; mt < 2; ++mt)
#pragma unroll
        for (int ntp = 0; ntp < 2; ++ntp) {
            uint32_t ad = boff + (uint32_t)ntp * 4096 + sunit[mt];
            uint32_t xdh[4], xdl[4];
            LDSM4T(xdh, B2 + ad);
            LDSM4T(xdl, B3 + ad);
            uint32_t hnh[4], hnl[4], sh[4], sl[4];
#pragma unroll
            for (int q = 0; q < 4; ++q) {
                int nt = 2 * ntp + (q >> 1), hh = q & 1;
                float xd0 = bflo_f(xdh[q]) + bflo_f(xdl[q]);
                float xd1 = bfhi_f(xdh[q]) + bfhi_f(xdl[q]);
                float xh0 = gated(flt[mt][nt][hh * 2 + 0], acc[mt][nt][hh * 2 + 0]);
                float xh1 = gated(flt[mt][nt][hh * 2 + 1], acc[mt][nt][hh * 2 + 1]);
                float hn0 = xh0 + xd0, hn1 = xh1 + xd1;
                uint32_t h2 = cvt_bf16x2(hn1, hn0);
                hnh[q] = h2;
                hnl[q] = cvt_bf16x2(hn1 - bfhi_f(h2), hn0 - bflo_f(h2));
                uint32_t x2 = cvt_bf16x2(xh1, xh0);
                sh[q] = x2;
                sl[q] = cvt_bf16x2(xh1 - bfhi_f(x2), xh0 - bflo_f(x2));
            }
            STSM4T(B5 + ad, hnh);
            STSM4T(B6 + ad, hnl);
            STSM4T(B2 + ad, sh);   // xh overwrites xdil (per-warp disjoint regions)
            STSM4T(B3 + ad, sl);
        }
    __syncthreads();

    // ======== h_next image -> global ========
    {
        char* oih = (char*)&g_img[1 - ping][blk][0][0];
        char* oil = (char*)&g_img[1 - ping][blk][1][0];
#pragma unroll
        for (int j = 0; j < 4; ++j)
            *(uint4*)(oih + tid * 16 + j * 8192) = *(const uint4*)(smem + SMB(5) + tid * 16 + j * 8192);
#pragma unroll
        for (int j = 0; j < 4; ++j)
            *(uint4*)(oil + tid * 16 + j * 8192) = *(const uint4*)(smem + SMB(6) + tid * 16 + j * 8192);
    }
    init_acc(b_skip + layer * CC);
    CP_WAIT(0);                // C6 (w_skip) done

    // ======== G4: skip = Wk (x) xh ========
    mma_mat3(acc, B0, B1, B2, B3, aoff, boff, lmask, asel, bsel);
#pragma unroll
    for (int mt = 0; mt < 2; ++mt)
#pragma unroll
        for (int nt = 0; nt < 4; ++nt)
#pragma unroll
            for (int hh = 0; hh < 2; ++hh) {
                int o  = wm * 32 + mt * 16 + hh * 8 + (lane >> 2);
                int tg = t0 + wn * 32 + nt * 8 + (lane & 3) * 2;
                *(float2*)(skips + (size_t)o * TLEN + tg) =
                    make_float2(acc[mt][nt][hh * 2 + 0], acc[mt][nt][hh * 2 + 1]);
            }
}

// ---------------- host ----------------
extern "C" void kernel_launch(void* const* d_in, const int* in_sizes, int n_in,
                              void* d_out, int out_size)
{
    const float* x      = (const float*)d_in[0];
    const float* w_in   = (const float*)d_in[1];
    const float* b_in   = (const float*)d_in[2];
    const float* w_dil  = (const float*)d_in[3];
    const float* b_dil  = (const float*)d_in[4];
    const float* w_tanh = (const float*)d_in[5];
    const float* b_tanh = (const float*)d_in[6];
    const float* w_sig  = (const float*)d_in[7];
    const float* b_sig  = (const float*)d_in[8];
    const float* w_skip = (const float*)d_in[9];
    const float* b_skip = (const float*)d_in[10];
    float* out = (float*)d_out;

    cudaFuncSetAttribute(layer_kernel,
                         cudaFuncAttributeMaxDynamicSharedMemorySize, SMEM_TOTAL);

    prep_weights<<<(LL * 5 * CC * CC + 255) / 256, 256>>>(w_dil, w_tanh, w_sig, w_skip);
    input_conv<<<(BB * CC * TLEN / 4 + 255) / 256, 256>>>(x, w_in, b_in);
    img_build<<<NTILE, 512>>>();

    const int dils[LL] = {1, 2, 4, 8, 16, 32, 64, 128, 256, 512,
                          1, 2, 4, 8, 16, 32, 64, 128, 256, 512};
    for (int i = 0; i < LL; ++i) {
        layer_kernel<<<(BB * TLEN) / TT, 512, SMEM_TOTAL>>>(
            i, dils[i], i & 1, b_dil, b_tanh, b_sig, b_skip, out);
    }
}